// round 2
// baseline (speedup 1.0000x reference)
#include <cuda_runtime.h>
#include <cuda_bf16.h>
#include <cstdint>
#include <math.h>

#define SEQ 4096
#define EMB 256
#define HID 256
#define G4  1024     // 4*HID
#define NTAG 32
#define START_TAG 30
#define STOP_TAG 31
#define NEGV -10000.0f

// ---------------- scratch (device globals; no runtime allocation) ----------------
__device__ float g_xg[2u * SEQ * G4];      // 32 MB: input-gate preactivations per direction
__device__ float g_hs[SEQ * 2u * HID];     // 8 MB: concatenated hidden states [s][dir*256+h]
__device__ float g_feats[SEQ * NTAG];      // 512 KB

// ---------------- helpers ----------------
__device__ __forceinline__ float sigm(float x) { return 1.0f / (1.0f + expf(-x)); }

__device__ __forceinline__ uint32_t smem_u32(const void* p) {
    uint32_t a;
    asm("{ .reg .u64 t; cvta.to.shared.u64 t, %1; cvt.u32.u64 %0, t; }" : "=r"(a) : "l"(p));
    return a;
}
__device__ __forceinline__ uint32_t mapa_cluster(uint32_t addr, uint32_t rank) {
    uint32_t d;
    asm("mapa.shared::cluster.u32 %0, %1, %2;" : "=r"(d) : "r"(addr), "r"(rank));
    return d;
}
__device__ __forceinline__ void st_cluster_f32(uint32_t addr, float v) {
    asm volatile("st.shared::cluster.f32 [%0], %1;" :: "r"(addr), "f"(v) : "memory");
}
__device__ __forceinline__ void cluster_sync() {
    asm volatile("barrier.cluster.arrive.aligned;" ::: "memory");
    asm volatile("barrier.cluster.wait.aligned;" ::: "memory");
}

// ---------------- Kernel A: xg[dir][s][:] = emb_row(s,dir) @ W_ih^T + b ----------------
// grid (SEQ/16, 2), block 256
__global__ void __launch_bounds__(256) xg_kernel(
    const int* __restrict__ sent, const float* __restrict__ emb,
    const float* __restrict__ w_ih_f, const float* __restrict__ b_f,
    const float* __restrict__ w_ih_b, const float* __restrict__ b_b)
{
    const int dir = blockIdx.y;
    const int s0 = blockIdx.x * 16;
    const float* __restrict__ w = dir ? w_ih_b : w_ih_f;
    const float* __restrict__ b = dir ? b_b : b_f;

    __shared__ __align__(16) float es[16 * EMB];
    for (int i = threadIdx.x; i < 16 * EMB; i += 256) {
        int ss = i >> 8, e = i & 255;
        int s = s0 + ss;
        int tok = sent[dir ? (SEQ - 1 - s) : s];
        es[ss * EMB + e] = emb[(size_t)tok * EMB + e];
    }
    __syncthreads();

    const int t = threadIdx.x;
    float acc[4][16];
#pragma unroll
    for (int rr = 0; rr < 4; rr++)
#pragma unroll
        for (int ss = 0; ss < 16; ss++) acc[rr][ss] = 0.0f;

    for (int e = 0; e < EMB; e += 4) {
        float4 ev[16];
#pragma unroll
        for (int ss = 0; ss < 16; ss++) ev[ss] = *(const float4*)&es[ss * EMB + e];
#pragma unroll
        for (int rr = 0; rr < 4; rr++) {
            int R = rr * 256 + t;
            float4 w4 = __ldg((const float4*)&w[(size_t)R * EMB + e]);
#pragma unroll
            for (int ss = 0; ss < 16; ss++) {
                acc[rr][ss] += w4.x * ev[ss].x;
                acc[rr][ss] += w4.y * ev[ss].y;
                acc[rr][ss] += w4.z * ev[ss].z;
                acc[rr][ss] += w4.w * ev[ss].w;
            }
        }
    }
    float* xg = g_xg + (size_t)dir * SEQ * G4;
#pragma unroll
    for (int rr = 0; rr < 4; rr++) {
        int R = rr * 256 + t;
        float bv = b[R];
#pragma unroll
        for (int ss = 0; ss < 16; ss++)
            xg[(size_t)(s0 + ss) * G4 + R] = acc[rr][ss] + bv;
    }
}

// ---------------- Kernel B: BiLSTM recurrence, 8-CTA cluster per direction ----------------
// grid 16 blocks (cluster 8) x 512 threads. CTA k owns hidden units [k*32, k*32+32).
// thread t: r = t>>2 (local gate-row 0..127), q = t&3 (quarter of the 256-dot).
__global__ void __cluster_dims__(8, 1, 1) __launch_bounds__(512, 1)
lstm_kernel(const float* __restrict__ w_hh_f, const float* __restrict__ w_hh_b,
            const float* __restrict__ h0, const float* __restrict__ c0)
{
    const int dir = blockIdx.x >> 3;
    const int k   = blockIdx.x & 7;
    const float* __restrict__ w = dir ? w_hh_b : w_hh_f;

    const int tid  = threadIdx.x;
    const int r    = tid >> 2;
    const int q    = tid & 3;
    const int gate = r >> 5;
    const int jj   = r & 31;
    const int R    = gate * 256 + k * 32 + jj;   // global gate row

    __shared__ __align__(16) float h_s[HID];
    __shared__ float gbuf[128];
    __shared__ float cbuf[32];

    // cache this thread's 64 weights in registers
    float wreg[64];
#pragma unroll
    for (int i = 0; i < 64; i += 4) {
        float4 w4 = __ldg((const float4*)&w[(size_t)R * HID + q * 64 + i]);
        wreg[i] = w4.x; wreg[i + 1] = w4.y; wreg[i + 2] = w4.z; wreg[i + 3] = w4.w;
    }
    if (tid < HID) h_s[tid] = h0[dir * HID + tid];
    if (tid < 32)  cbuf[tid] = c0[dir * HID + k * 32 + tid];
    __syncthreads();
    cluster_sync();   // all CTAs initialized before any DSMEM writes

    const float* __restrict__ xg = g_xg + (size_t)dir * SEQ * G4;

#pragma unroll 1
    for (int t = 0; t < SEQ; t++) {
        float xgv = 0.0f;
        if (q == 0) xgv = __ldg(&xg[(size_t)t * G4 + R]);   // hidden under the dot

        float acc = 0.0f;
        const float4* hq = (const float4*)&h_s[q * 64];
#pragma unroll
        for (int i = 0; i < 16; i++) {
            float4 h4 = hq[i];
            acc += wreg[4 * i]     * h4.x;
            acc += wreg[4 * i + 1] * h4.y;
            acc += wreg[4 * i + 2] * h4.z;
            acc += wreg[4 * i + 3] * h4.w;
        }
        acc += __shfl_xor_sync(0xffffffffu, acc, 1);
        acc += __shfl_xor_sync(0xffffffffu, acc, 2);
        if (q == 0) gbuf[r] = acc + xgv;
        __syncthreads();

        if (tid < 32) {
            float gi = sigm(gbuf[tid]);
            float gf = sigm(gbuf[32 + tid]);
            float gg = tanhf(gbuf[64 + tid]);
            float go = sigm(gbuf[96 + tid]);
            float c  = gf * cbuf[tid] + gi * gg;
            cbuf[tid] = c;
            float hv = go * tanhf(c);
            int hidx = k * 32 + tid;
            int s_out = dir ? (SEQ - 1 - t) : t;
            g_hs[(size_t)s_out * (2 * HID) + dir * HID + hidx] = hv;
            // broadcast h chunk to all 8 CTAs of this cluster (incl. self)
            uint32_t la = smem_u32(&h_s[hidx]);
#pragma unroll
            for (uint32_t p = 0; p < 8; p++)
                st_cluster_f32(mapa_cluster(la, p), hv);
        }
        cluster_sync();   // release DSMEM writes / acquire before next dot
    }
}

// ---------------- Kernel C: feats = [hs_f | hs_b] @ lin_w^T + lin_b ----------------
// grid SEQ, block 256 (8 chunks x 32 tags)
__global__ void __launch_bounds__(256) feats_kernel(
    const float* __restrict__ lin_w, const float* __restrict__ lin_b)
{
    const int s = blockIdx.x;
    const int tag = threadIdx.x & 31;
    const int ch  = threadIdx.x >> 5;
    const float* __restrict__ hrow = g_hs + (size_t)s * (2 * HID) + ch * 64;
    const float* __restrict__ wrow = lin_w + (size_t)tag * (2 * HID) + ch * 64;
    float a = 0.0f;
#pragma unroll
    for (int i = 0; i < 64; i += 4) {
        float4 h4 = *(const float4*)&hrow[i];
        float4 w4 = __ldg((const float4*)&wrow[i]);
        a += h4.x * w4.x + h4.y * w4.y + h4.z * w4.z + h4.w * w4.w;
    }
    __shared__ float part[256];
    part[threadIdx.x] = a;
    __syncthreads();
    if (threadIdx.x < 32) {
        float sum = lin_b[threadIdx.x];
#pragma unroll
        for (int c = 0; c < 8; c++) sum += part[c * 32 + threadIdx.x];
        g_feats[(size_t)s * NTAG + threadIdx.x] = sum;
    }
}

// ---------------- Kernel D: Viterbi + backtrack (1 warp, bp in dynamic smem) ----------------
extern __shared__ unsigned char bpbuf[];   // SEQ*NTAG bytes

__global__ void __launch_bounds__(32) viterbi_kernel(
    const float* __restrict__ trans, float* __restrict__ out, int out_size)
{
    const int n = threadIdx.x;   // next-tag this lane owns
    float trow[32];
#pragma unroll
    for (int p = 0; p < 32; p++) trow[p] = trans[n * NTAG + p];
    const float tstop = trans[STOP_TAG * NTAG + n];

    float myfv = (n == START_TAG) ? 0.0f : NEGV;
    float fnext = __ldg(&g_feats[n]);

#pragma unroll 1
    for (int t = 0; t < SEQ; t++) {
        float feat = fnext;
        if (t + 1 < SEQ) fnext = __ldg(&g_feats[(size_t)(t + 1) * NTAG + n]);

        float sc[32];
        int ix[32];
#pragma unroll
        for (int p = 0; p < 32; p++) {
            sc[p] = __shfl_sync(0xffffffffu, myfv, p) + trow[p];
            ix[p] = p;
        }
        // argmax tree, first-index tie-break (strict > keeps lower index)
#pragma unroll
        for (int off = 1; off < 32; off <<= 1) {
#pragma unroll
            for (int i = 0; i < 32; i += 2 * off) {
                if (sc[i + off] > sc[i]) { sc[i] = sc[i + off]; ix[i] = ix[i + off]; }
            }
        }
        myfv = sc[0] + feat;
        bpbuf[t * NTAG + n] = (unsigned char)ix[0];
    }

    // terminal transition + warp argmax (first index on ties)
    float bv = myfv + tstop;
    int bi = n;
#pragma unroll
    for (int off = 16; off; off >>= 1) {
        float ov = __shfl_xor_sync(0xffffffffu, bv, off);
        int   oi = __shfl_xor_sync(0xffffffffu, bi, off);
        if (ov > bv || (ov == bv && oi < bi)) { bv = ov; bi = oi; }
    }

    if (n == 0) {
        const bool has_score = (out_size >= SEQ + 1);
        const int base = has_score ? 1 : 0;
        if (has_score && out_size > 0) out[0] = bv;
        int idx = bi;
        for (int t = SEQ - 1; t >= 0; t--) {
            int o = base + t;
            if (o < out_size) out[o] = (float)idx;
            idx = bpbuf[t * NTAG + idx];
        }
    }
}

// ---------------- launch ----------------
extern "C" void kernel_launch(void* const* d_in, const int* in_sizes, int n_in,
                              void* d_out, int out_size)
{
    const int*   sentence = (const int*)  d_in[0];
    const float* h0       = (const float*)d_in[1];
    const float* c0       = (const float*)d_in[2];
    const float* embedding= (const float*)d_in[3];
    const float* w_ih_f   = (const float*)d_in[4];
    const float* w_hh_f   = (const float*)d_in[5];
    const float* b_f      = (const float*)d_in[6];
    const float* w_ih_b   = (const float*)d_in[7];
    const float* w_hh_b   = (const float*)d_in[8];
    const float* b_b      = (const float*)d_in[9];
    const float* lin_w    = (const float*)d_in[10];
    const float* lin_b    = (const float*)d_in[11];
    const float* trans    = (const float*)d_in[12];
    float* out = (float*)d_out;

    xg_kernel<<<dim3(SEQ / 16, 2), 256>>>(sentence, embedding, w_ih_f, b_f, w_ih_b, b_b);
    lstm_kernel<<<16, 512>>>(w_hh_f, w_hh_b, h0, c0);
    feats_kernel<<<SEQ, 256>>>(lin_w, lin_b);

    const int vit_smem = SEQ * NTAG;   // 128 KB backpointers
    cudaFuncSetAttribute(viterbi_kernel, cudaFuncAttributeMaxDynamicSharedMemorySize, vit_smem);
    viterbi_kernel<<<1, 32, vit_smem>>>(trans, out, out_size);
}

// round 3
// speedup vs baseline: 3.0035x; 3.0035x over previous
#include <cuda_runtime.h>
#include <cuda_bf16.h>
#include <cstdint>
#include <math.h>

#define SEQ 4096
#define EMB 256
#define HID 256
#define G4  1024     // 4*HID
#define NTAG 32
#define START_TAG 30
#define STOP_TAG 31
#define NEGV -10000.0f
#define HB 68        // padded chunk stride (floats) for conflict-free LDS

// ---------------- scratch (device globals; no runtime allocation) ----------------
__device__ float g_xg[2u * SEQ * G4];      // 32 MB: gate preactivations per direction
__device__ float g_hs[SEQ * 2u * HID];     // 8 MB: concatenated hidden states
__device__ float g_feats[SEQ * NTAG];      // 512 KB

// ---------------- helpers ----------------
__device__ __forceinline__ float sigm_fast(float x) {
    return __fdividef(1.0f, 1.0f + __expf(-x));
}
__device__ __forceinline__ float tanh_fast(float x) {
    // 1 - 2/(e^{2x}+1); saturates correctly at +-inf
    return 1.0f - __fdividef(2.0f, __expf(2.0f * x) + 1.0f);
}

__device__ __forceinline__ uint32_t smem_u32(const void* p) {
    uint32_t a;
    asm("{ .reg .u64 t; cvta.to.shared.u64 t, %1; cvt.u32.u64 %0, t; }" : "=r"(a) : "l"(p));
    return a;
}
__device__ __forceinline__ uint32_t mapa_cluster(uint32_t addr, uint32_t rank) {
    uint32_t d;
    asm("mapa.shared::cluster.u32 %0, %1, %2;" : "=r"(d) : "r"(addr), "r"(rank));
    return d;
}
__device__ __forceinline__ void st_cluster_f32(uint32_t addr, float v) {
    asm volatile("st.shared::cluster.f32 [%0], %1;" :: "r"(addr), "f"(v) : "memory");
}
__device__ __forceinline__ void cluster_sync() {
    asm volatile("barrier.cluster.arrive.aligned;" ::: "memory");
    asm volatile("barrier.cluster.wait.aligned;" ::: "memory");
}
__device__ __forceinline__ void mbar_wait_cluster(uint32_t addr, uint32_t parity) {
    asm volatile(
        "{\n\t.reg .pred P;\n\t"
        "WL_%=:\n\t"
        "mbarrier.try_wait.parity.acquire.cluster.shared::cta.b64 P, [%0], %1;\n\t"
        "@P bra WD_%=;\n\t"
        "bra WL_%=;\n\t"
        "WD_%=:\n\t}"
        :: "r"(addr), "r"(parity) : "memory");
}
__device__ __forceinline__ void mbar_arrive_remote(uint32_t local_addr, uint32_t rank) {
    asm volatile(
        "{\n\t.reg .b32 ra;\n\t"
        "mapa.shared::cluster.u32 ra, %0, %1;\n\t"
        "mbarrier.arrive.release.cluster.shared::cluster.b64 _, [ra];\n\t}"
        :: "r"(local_addr), "r"(rank) : "memory");
}

// ---- f32x2 packed math (Blackwell FFMA2) ----
__device__ __forceinline__ unsigned long long pack2(float a, float b) {
    unsigned long long r;
    asm("mov.b64 %0, {%1, %2};" : "=l"(r) : "f"(a), "f"(b));
    return r;
}
__device__ __forceinline__ void ffma2(unsigned long long& d, unsigned long long a, unsigned long long b) {
    asm("fma.rn.f32x2 %0, %1, %2, %0;" : "+l"(d) : "l"(a), "l"(b));
}
__device__ __forceinline__ unsigned long long add2(unsigned long long a, unsigned long long b) {
    unsigned long long r;
    asm("add.rn.f32x2 %0, %1, %2;" : "=l"(r) : "l"(a), "l"(b));
    return r;
}
__device__ __forceinline__ float sum2(unsigned long long a) {
    float lo, hi;
    asm("mov.b64 {%0, %1}, %2;" : "=f"(lo), "=f"(hi) : "l"(a));
    return lo + hi;
}

// ---------------- Kernel A: xg[dir][s][:] = emb_row(s,dir) @ W_ih^T + b ----------------
__global__ void __launch_bounds__(256) xg_kernel(
    const int* __restrict__ sent, const float* __restrict__ emb,
    const float* __restrict__ w_ih_f, const float* __restrict__ b_f,
    const float* __restrict__ w_ih_b, const float* __restrict__ b_b)
{
    const int dir = blockIdx.y;
    const int s0 = blockIdx.x * 16;
    const float* __restrict__ w = dir ? w_ih_b : w_ih_f;
    const float* __restrict__ b = dir ? b_b : b_f;

    __shared__ __align__(16) float es[16 * EMB];
    for (int i = threadIdx.x; i < 16 * EMB; i += 256) {
        int ss = i >> 8, e = i & 255;
        int s = s0 + ss;
        int tok = sent[dir ? (SEQ - 1 - s) : s];
        es[ss * EMB + e] = emb[(size_t)tok * EMB + e];
    }
    __syncthreads();

    const int t = threadIdx.x;
    float acc[4][16];
#pragma unroll
    for (int rr = 0; rr < 4; rr++)
#pragma unroll
        for (int ss = 0; ss < 16; ss++) acc[rr][ss] = 0.0f;

    for (int e = 0; e < EMB; e += 4) {
        float4 ev[16];
#pragma unroll
        for (int ss = 0; ss < 16; ss++) ev[ss] = *(const float4*)&es[ss * EMB + e];
#pragma unroll
        for (int rr = 0; rr < 4; rr++) {
            int R = rr * 256 + t;
            float4 w4 = __ldg((const float4*)&w[(size_t)R * EMB + e]);
#pragma unroll
            for (int ss = 0; ss < 16; ss++) {
                acc[rr][ss] += w4.x * ev[ss].x;
                acc[rr][ss] += w4.y * ev[ss].y;
                acc[rr][ss] += w4.z * ev[ss].z;
                acc[rr][ss] += w4.w * ev[ss].w;
            }
        }
    }
    float* xg = g_xg + (size_t)dir * SEQ * G4;
#pragma unroll
    for (int rr = 0; rr < 4; rr++) {
        int R = rr * 256 + t;
        float bv = b[R];
#pragma unroll
        for (int ss = 0; ss < 16; ss++)
            xg[(size_t)(s0 + ss) * G4 + R] = acc[rr][ss] + bv;
    }
}

// ---------------- Kernel B: BiLSTM recurrence, 8-CTA cluster, mbarrier-pipelined ----------------
// grid 16 (cluster 8) x 512. CTA k owns hidden units [k*32, k*32+32).
// thread: r=tid>>2 local gate row (0..127), q=tid&3 quarter of the 256-dot.
__global__ void __cluster_dims__(8, 1, 1) __launch_bounds__(512, 1)
lstm_kernel(const float* __restrict__ w_hh_f, const float* __restrict__ w_hh_b,
            const float* __restrict__ h0, const float* __restrict__ c0)
{
    const int dir = blockIdx.x >> 3;
    const int k   = blockIdx.x & 7;
    const float* __restrict__ w = dir ? w_hh_b : w_hh_f;

    const int tid  = threadIdx.x;
    const int r    = tid >> 2;
    const int q    = tid & 3;
    const int gate = r >> 5;
    const int jj   = r & 31;
    const int R    = gate * 256 + k * 32 + jj;

    __shared__ __align__(16) float hbuf[2][4 * HB];   // padded, double-buffered h
    __shared__ float gbuf[128];
    __shared__ float cbuf[32];
    __shared__ __align__(8) unsigned long long mb;

    // cache 64 weights as 32 packed f32x2
    unsigned long long w2[32];
#pragma unroll
    for (int i = 0; i < 16; i++) {
        float4 w4 = __ldg((const float4*)&w[(size_t)R * HID + q * 64 + 4 * i]);
        w2[2 * i]     = pack2(w4.x, w4.y);
        w2[2 * i + 1] = pack2(w4.z, w4.w);
    }
    const uint32_t mba = smem_u32(&mb);
    if (tid == 0)
        asm volatile("mbarrier.init.shared.b64 [%0], 8;" :: "r"(mba) : "memory");
    if (tid < HID) hbuf[0][(tid >> 6) * HB + (tid & 63)] = h0[dir * HID + tid];
    if (tid < 32)  cbuf[tid] = c0[dir * HID + k * 32 + tid];
    __syncthreads();
    cluster_sync();   // mbarrier + h0 visible cluster-wide before any step

    const float* __restrict__ xg = g_xg + (size_t)dir * SEQ * G4;
    float xgv = (q == 0) ? __ldg(&xg[R]) : 0.0f;
    int ph = 0;

#pragma unroll 1
    for (int t = 0; t < SEQ; t++) {
        if (t) { mbar_wait_cluster(mba, (uint32_t)ph); ph ^= 1; }

        const ulonglong2* hq = (const ulonglong2*)&hbuf[t & 1][q * HB];
        unsigned long long a0 = 0, a1 = 0, a2 = 0, a3 = 0;
#pragma unroll
        for (int i = 0; i < 16; i += 2) {
            ulonglong2 hv0 = hq[i];
            ulonglong2 hv1 = hq[i + 1];
            ffma2(a0, w2[2 * i],     hv0.x);
            ffma2(a1, w2[2 * i + 1], hv0.y);
            ffma2(a2, w2[2 * i + 2], hv1.x);
            ffma2(a3, w2[2 * i + 3], hv1.y);
        }
        float acc = sum2(add2(add2(a0, a1), add2(a2, a3)));
        acc += __shfl_xor_sync(0xffffffffu, acc, 1);
        acc += __shfl_xor_sync(0xffffffffu, acc, 2);
        if (q == 0) {
            gbuf[r] = acc + xgv;
            if (t + 1 < SEQ) xgv = __ldg(&xg[(size_t)(t + 1) * G4 + R]);  // prefetch
        }
        __syncthreads();

        if (tid < 32) {
            float gi = sigm_fast(gbuf[tid]);
            float gf = sigm_fast(gbuf[32 + tid]);
            float gg = tanh_fast(gbuf[64 + tid]);
            float go = sigm_fast(gbuf[96 + tid]);
            float c  = gf * cbuf[tid] + gi * gg;
            cbuf[tid] = c;
            float hv = go * tanh_fast(c);
            int hidx = k * 32 + tid;
            int s_out = dir ? (SEQ - 1 - t) : t;
            g_hs[(size_t)s_out * (2 * HID) + dir * HID + hidx] = hv;
            if (t + 1 < SEQ) {
                uint32_t la = smem_u32(&hbuf[(t + 1) & 1][0])
                            + (uint32_t)(((hidx >> 6) * HB + (hidx & 63)) * 4);
#pragma unroll
                for (uint32_t p = 0; p < 8; p++)
                    st_cluster_f32(mapa_cluster(la, p), hv);
                __syncwarp();
                if (tid < 8) mbar_arrive_remote(mba, (uint32_t)tid);
            }
        }
    }
    cluster_sync();   // no CTA exits with peers' remote ops possibly in flight
}

// ---------------- Kernel C: feats = [hs_f | hs_b] @ lin_w^T + lin_b ----------------
__global__ void __launch_bounds__(256) feats_kernel(
    const float* __restrict__ lin_w, const float* __restrict__ lin_b)
{
    const int s = blockIdx.x;
    const int tag = threadIdx.x & 31;
    const int ch  = threadIdx.x >> 5;
    const float* __restrict__ hrow = g_hs + (size_t)s * (2 * HID) + ch * 64;
    const float* __restrict__ wrow = lin_w + (size_t)tag * (2 * HID) + ch * 64;
    float a = 0.0f;
#pragma unroll
    for (int i = 0; i < 64; i += 4) {
        float4 h4 = *(const float4*)&hrow[i];
        float4 w4 = __ldg((const float4*)&wrow[i]);
        a += h4.x * w4.x + h4.y * w4.y + h4.z * w4.z + h4.w * w4.w;
    }
    __shared__ float part[256];
    part[threadIdx.x] = a;
    __syncthreads();
    if (threadIdx.x < 32) {
        float sum = lin_b[threadIdx.x];
#pragma unroll
        for (int c = 0; c < 8; c++) sum += part[c * 32 + threadIdx.x];
        g_feats[(size_t)s * NTAG + threadIdx.x] = sum;
    }
}

// ---------------- Kernel D: Viterbi + backtrack (1 warp, bp in dynamic smem) ----------------
extern __shared__ unsigned char bpbuf[];   // SEQ*NTAG bytes

__global__ void __launch_bounds__(32) viterbi_kernel(
    const float* __restrict__ trans, float* __restrict__ out, int out_size)
{
    const int n = threadIdx.x;
    float trow[32];
#pragma unroll
    for (int p = 0; p < 32; p++) trow[p] = trans[n * NTAG + p];
    const float tstop = trans[STOP_TAG * NTAG + n];

    float myfv = (n == START_TAG) ? 0.0f : NEGV;
    float fnext = __ldg(&g_feats[n]);

#pragma unroll 1
    for (int t = 0; t < SEQ; t++) {
        float feat = fnext;
        if (t + 1 < SEQ) fnext = __ldg(&g_feats[(size_t)(t + 1) * NTAG + n]);

        float sc[32];
        int ix[32];
#pragma unroll
        for (int p = 0; p < 32; p++) {
            sc[p] = __shfl_sync(0xffffffffu, myfv, p) + trow[p];
            ix[p] = p;
        }
#pragma unroll
        for (int off = 1; off < 32; off <<= 1) {
#pragma unroll
            for (int i = 0; i < 32; i += 2 * off) {
                if (sc[i + off] > sc[i]) { sc[i] = sc[i + off]; ix[i] = ix[i + off]; }
            }
        }
        myfv = sc[0] + feat;
        bpbuf[t * NTAG + n] = (unsigned char)ix[0];
    }

    float bv = myfv + tstop;
    int bi = n;
#pragma unroll
    for (int off = 16; off; off >>= 1) {
        float ov = __shfl_xor_sync(0xffffffffu, bv, off);
        int   oi = __shfl_xor_sync(0xffffffffu, bi, off);
        if (ov > bv || (ov == bv && oi < bi)) { bv = ov; bi = oi; }
    }

    if (n == 0) {
        const bool has_score = (out_size >= SEQ + 1);
        const int base = has_score ? 1 : 0;
        if (has_score && out_size > 0) out[0] = bv;
        int idx = bi;
        for (int t = SEQ - 1; t >= 0; t--) {
            int o = base + t;
            if (o < out_size) out[o] = (float)idx;
            idx = bpbuf[t * NTAG + idx];
        }
    }
}

// ---------------- launch ----------------
extern "C" void kernel_launch(void* const* d_in, const int* in_sizes, int n_in,
                              void* d_out, int out_size)
{
    const int*   sentence = (const int*)  d_in[0];
    const float* h0       = (const float*)d_in[1];
    const float* c0       = (const float*)d_in[2];
    const float* embedding= (const float*)d_in[3];
    const float* w_ih_f   = (const float*)d_in[4];
    const float* w_hh_f   = (const float*)d_in[5];
    const float* b_f      = (const float*)d_in[6];
    const float* w_ih_b   = (const float*)d_in[7];
    const float* w_hh_b   = (const float*)d_in[8];
    const float* b_b      = (const float*)d_in[9];
    const float* lin_w    = (const float*)d_in[10];
    const float* lin_b    = (const float*)d_in[11];
    const float* trans    = (const float*)d_in[12];
    float* out = (float*)d_out;

    xg_kernel<<<dim3(SEQ / 16, 2), 256>>>(sentence, embedding, w_ih_f, b_f, w_ih_b, b_b);
    lstm_kernel<<<16, 512>>>(w_hh_f, w_hh_b, h0, c0);
    feats_kernel<<<SEQ, 256>>>(lin_w, lin_b);

    const int vit_smem = SEQ * NTAG;   // 128 KB backpointers
    cudaFuncSetAttribute(viterbi_kernel, cudaFuncAttributeMaxDynamicSharedMemorySize, vit_smem);
    viterbi_kernel<<<1, 32, vit_smem>>>(trans, out, out_size);
}

// round 4
// speedup vs baseline: 3.6795x; 1.2251x over previous
#include <cuda_runtime.h>
#include <cuda_bf16.h>
#include <cstdint>
#include <math.h>

#define SEQ 4096
#define EMB 256
#define HID 256
#define G4  1024     // 4*HID
#define NTAG 32
#define START_TAG 30
#define STOP_TAG 31
#define NEGV -10000.0f
#define HB 68        // padded chunk stride (floats) for conflict-free LDS

// ---------------- scratch (device globals; no runtime allocation) ----------------
__device__ float g_xg[2u * SEQ * G4];      // 32 MB: gate preactivations per direction
__device__ float g_hs[SEQ * 2u * HID];     // 8 MB: concatenated hidden states
__device__ float g_feats[SEQ * NTAG];      // 512 KB

// ---------------- helpers ----------------
__device__ __forceinline__ float sigm_fast(float x) {
    return __fdividef(1.0f, 1.0f + __expf(-x));
}
__device__ __forceinline__ float tanh_fast(float x) {
    return 1.0f - __fdividef(2.0f, __expf(2.0f * x) + 1.0f);
}

__device__ __forceinline__ uint32_t smem_u32(const void* p) {
    uint32_t a;
    asm("{ .reg .u64 t; cvta.to.shared.u64 t, %1; cvt.u32.u64 %0, t; }" : "=r"(a) : "l"(p));
    return a;
}
__device__ __forceinline__ void cluster_sync() {
    asm volatile("barrier.cluster.arrive.aligned;" ::: "memory");
    asm volatile("barrier.cluster.wait.aligned;" ::: "memory");
}
__device__ __forceinline__ void mbar_init(uint32_t addr, uint32_t cnt) {
    asm volatile("mbarrier.init.shared.b64 [%0], %1;" :: "r"(addr), "r"(cnt) : "memory");
}
__device__ __forceinline__ void mbar_expect_tx(uint32_t addr, uint32_t bytes) {
    asm volatile("mbarrier.arrive.expect_tx.shared.b64 _, [%0], %1;"
                 :: "r"(addr), "r"(bytes) : "memory");
}
__device__ __forceinline__ void mbar_wait_cta(uint32_t addr, uint32_t parity) {
    asm volatile(
        "{\n\t.reg .pred P;\n\t"
        "WL_%=:\n\t"
        "mbarrier.try_wait.parity.acquire.cta.shared::cta.b64 P, [%0], %1;\n\t"
        "@P bra WD_%=;\n\t"
        "bra WL_%=;\n\t"
        "WD_%=:\n\t}"
        :: "r"(addr), "r"(parity) : "memory");
}
// async store into peer CTA's smem, counting 4 bytes toward peer's mbarrier
__device__ __forceinline__ void st_async_f32(uint32_t laddr, float v, uint32_t lmbar, uint32_t rank) {
    asm volatile(
        "{\n\t.reg .b32 ra, rm;\n\t"
        "mapa.shared::cluster.u32 ra, %0, %2;\n\t"
        "mapa.shared::cluster.u32 rm, %3, %2;\n\t"
        "st.async.shared::cluster.mbarrier::complete_tx::bytes.f32 [ra], %1, [rm];\n\t}"
        :: "r"(laddr), "f"(v), "r"(rank), "r"(lmbar) : "memory");
}

// ---- f32x2 packed math (Blackwell FFMA2) ----
__device__ __forceinline__ unsigned long long pack2(float a, float b) {
    unsigned long long r;
    asm("mov.b64 %0, {%1, %2};" : "=l"(r) : "f"(a), "f"(b));
    return r;
}
__device__ __forceinline__ void ffma2(unsigned long long& d, unsigned long long a, unsigned long long b) {
    asm("fma.rn.f32x2 %0, %1, %2, %0;" : "+l"(d) : "l"(a), "l"(b));
}
__device__ __forceinline__ unsigned long long add2(unsigned long long a, unsigned long long b) {
    unsigned long long r;
    asm("add.rn.f32x2 %0, %1, %2;" : "=l"(r) : "l"(a), "l"(b));
    return r;
}
__device__ __forceinline__ float sum2(unsigned long long a) {
    float lo, hi;
    asm("mov.b64 {%0, %1}, %2;" : "=f"(lo), "=f"(hi) : "l"(a));
    return lo + hi;
}

// ---------------- Kernel A: xg[dir][s][:] = emb_row(s,dir) @ W_ih^T + b ----------------
__global__ void __launch_bounds__(256) xg_kernel(
    const int* __restrict__ sent, const float* __restrict__ emb,
    const float* __restrict__ w_ih_f, const float* __restrict__ b_f,
    const float* __restrict__ w_ih_b, const float* __restrict__ b_b)
{
    const int dir = blockIdx.y;
    const int s0 = blockIdx.x * 16;
    const float* __restrict__ w = dir ? w_ih_b : w_ih_f;
    const float* __restrict__ b = dir ? b_b : b_f;

    __shared__ __align__(16) float es[16 * EMB];
    for (int i = threadIdx.x; i < 16 * EMB; i += 256) {
        int ss = i >> 8, e = i & 255;
        int s = s0 + ss;
        int tok = sent[dir ? (SEQ - 1 - s) : s];
        es[ss * EMB + e] = emb[(size_t)tok * EMB + e];
    }
    __syncthreads();

    const int t = threadIdx.x;
    float acc[4][16];
#pragma unroll
    for (int rr = 0; rr < 4; rr++)
#pragma unroll
        for (int ss = 0; ss < 16; ss++) acc[rr][ss] = 0.0f;

    for (int e = 0; e < EMB; e += 4) {
        float4 ev[16];
#pragma unroll
        for (int ss = 0; ss < 16; ss++) ev[ss] = *(const float4*)&es[ss * EMB + e];
#pragma unroll
        for (int rr = 0; rr < 4; rr++) {
            int R = rr * 256 + t;
            float4 w4 = __ldg((const float4*)&w[(size_t)R * EMB + e]);
#pragma unroll
            for (int ss = 0; ss < 16; ss++) {
                acc[rr][ss] += w4.x * ev[ss].x;
                acc[rr][ss] += w4.y * ev[ss].y;
                acc[rr][ss] += w4.z * ev[ss].z;
                acc[rr][ss] += w4.w * ev[ss].w;
            }
        }
    }
    float* xg = g_xg + (size_t)dir * SEQ * G4;
#pragma unroll
    for (int rr = 0; rr < 4; rr++) {
        int R = rr * 256 + t;
        float bv = b[R];
#pragma unroll
        for (int ss = 0; ss < 16; ss++)
            xg[(size_t)(s0 + ss) * G4 + R] = acc[rr][ss] + bv;
    }
}

// ---------------- Kernel B: BiLSTM recurrence, 8-CTA cluster, st.async + tx-mbarrier ----------------
// grid 16 (cluster 8) x 512. CTA k owns hidden units [k*32, k*32+32).
// lane layout: u=l>>4 (unit within warp), gate=(l>>2)&3, q=l&3 (quarter of 256-dot).
// warp w owns h-units {k*32 + 2w, k*32 + 2w + 1}.
__global__ void __cluster_dims__(8, 1, 1) __launch_bounds__(512, 1)
lstm_kernel(const float* __restrict__ w_hh_f, const float* __restrict__ w_hh_b,
            const float* __restrict__ h0, const float* __restrict__ c0)
{
    const int dir = blockIdx.x >> 3;
    const int k   = blockIdx.x & 7;
    const float* __restrict__ w = dir ? w_hh_b : w_hh_f;

    const int tid  = threadIdx.x;
    const int wp   = tid >> 5;
    const int l    = tid & 31;
    const int u    = l >> 4;
    const int gate = (l >> 2) & 3;
    const int q    = l & 3;
    const int hidx = k * 32 + wp * 2 + u;        // global h unit this thread serves
    const int R    = gate * 256 + hidx;          // gate row

    __shared__ __align__(16) float hbuf[2][4 * HB];
    __shared__ __align__(8) unsigned long long mbar[2];

    // 64 weights as 32 packed f32x2
    unsigned long long w2[32];
#pragma unroll
    for (int i = 0; i < 16; i++) {
        float4 w4 = __ldg((const float4*)&w[(size_t)R * HID + q * 64 + 4 * i]);
        w2[2 * i]     = pack2(w4.x, w4.y);
        w2[2 * i + 1] = pack2(w4.z, w4.w);
    }
    const uint32_t mb0 = smem_u32(&mbar[0]);
    const uint32_t mb1 = smem_u32(&mbar[1]);
    if (tid == 0) {
        mbar_init(mb0, 1);
        mbar_init(mb1, 1);
        mbar_expect_tx(mb0, 1024);   // armed for first use (consumed at step 2)
        mbar_expect_tx(mb1, 1024);   // armed for first use (consumed at step 1)
    }
    if (tid < HID) hbuf[0][(tid >> 6) * HB + (tid & 63)] = h0[dir * HID + tid];

    const bool producer = (l & 15) == 0;         // lanes 0 and 16
    float creg = producer ? c0[dir * HID + hidx] : 0.0f;

    __syncthreads();
    cluster_sync();   // mbarriers + h0 visible cluster-wide

    const float* __restrict__ xg = g_xg + (size_t)dir * SEQ * G4;
    float xgv = (q == 0) ? __ldg(&xg[R]) : 0.0f;

    const uint32_t hb0 = smem_u32(&hbuf[0][0]);
    const uint32_t hb1 = smem_u32(&hbuf[1][0]);
    const uint32_t slot_off = (uint32_t)(((hidx >> 6) * HB + (hidx & 63)) * 4);
    int ph0 = 0, ph1 = 0;

#pragma unroll 1
    for (int t = 0; t < SEQ; t++) {
        const int b = t & 1;
        if (t) {
            if (b) { mbar_wait_cta(mb1, (uint32_t)ph1); ph1 ^= 1;
                     if (tid == 0) mbar_expect_tx(mb1, 1024); }
            else   { mbar_wait_cta(mb0, (uint32_t)ph0); ph0 ^= 1;
                     if (tid == 0) mbar_expect_tx(mb0, 1024); }
        }

        const ulonglong2* hq = (const ulonglong2*)&hbuf[b][q * HB];
        unsigned long long a0 = 0, a1 = 0, a2 = 0, a3 = 0;
#pragma unroll
        for (int i = 0; i < 16; i += 2) {
            ulonglong2 hv0 = hq[i];
            ulonglong2 hv1 = hq[i + 1];
            ffma2(a0, w2[2 * i],     hv0.x);
            ffma2(a1, w2[2 * i + 1], hv0.y);
            ffma2(a2, w2[2 * i + 2], hv1.x);
            ffma2(a3, w2[2 * i + 3], hv1.y);
        }
        float acc = sum2(add2(add2(a0, a1), add2(a2, a3)));
        acc += __shfl_xor_sync(0xffffffffu, acc, 1);
        acc += __shfl_xor_sync(0xffffffffu, acc, 2);
        float gcur = acc + xgv;                         // valid on q==0 lanes
        if (q == 0 && t + 1 < SEQ)
            xgv = __ldg(&xg[(size_t)(t + 1) * G4 + R]); // prefetch next step

        const int sb = l & 16;
        float gi = __shfl_sync(0xffffffffu, gcur, sb);
        float gf = __shfl_sync(0xffffffffu, gcur, sb + 4);
        float gg = __shfl_sync(0xffffffffu, gcur, sb + 8);
        float go = __shfl_sync(0xffffffffu, gcur, sb + 12);

        if (producer) {
            gi = sigm_fast(gi);
            gf = sigm_fast(gf);
            gg = tanh_fast(gg);
            go = sigm_fast(go);
            creg = gf * creg + gi * gg;
            float hv = go * tanh_fast(creg);
            int s_out = dir ? (SEQ - 1 - t) : t;
            g_hs[(size_t)s_out * (2 * HID) + dir * HID + hidx] = hv;
            if (t + 1 < SEQ) {
                const uint32_t la = (((t + 1) & 1) ? hb1 : hb0) + slot_off;
                const uint32_t lm = ((t + 1) & 1) ? mb1 : mb0;
#pragma unroll
                for (uint32_t p = 0; p < 8; p++)
                    st_async_f32(la, hv, lm, p);
            }
        }
    }
    cluster_sync();   // keep smem alive until peers are done
}

// ---------------- Kernel C: feats = [hs_f | hs_b] @ lin_w^T + lin_b ----------------
__global__ void __launch_bounds__(256) feats_kernel(
    const float* __restrict__ lin_w, const float* __restrict__ lin_b)
{
    const int s = blockIdx.x;
    const int tag = threadIdx.x & 31;
    const int ch  = threadIdx.x >> 5;
    const float* __restrict__ hrow = g_hs + (size_t)s * (2 * HID) + ch * 64;
    const float* __restrict__ wrow = lin_w + (size_t)tag * (2 * HID) + ch * 64;
    float a = 0.0f;
#pragma unroll
    for (int i = 0; i < 64; i += 4) {
        float4 h4 = *(const float4*)&hrow[i];
        float4 w4 = __ldg((const float4*)&wrow[i]);
        a += h4.x * w4.x + h4.y * w4.y + h4.z * w4.z + h4.w * w4.w;
    }
    __shared__ float part[256];
    part[threadIdx.x] = a;
    __syncthreads();
    if (threadIdx.x < 32) {
        float sum = lin_b[threadIdx.x];
#pragma unroll
        for (int c = 0; c < 8; c++) sum += part[c * 32 + threadIdx.x];
        g_feats[(size_t)s * NTAG + threadIdx.x] = sum;
    }
}

// ---------------- Kernel D: Viterbi + backtrack (1 warp, bp in dynamic smem) ----------------
extern __shared__ unsigned char bpbuf[];   // SEQ*NTAG bytes

__global__ void __launch_bounds__(32) viterbi_kernel(
    const float* __restrict__ trans, float* __restrict__ out, int out_size)
{
    const int n = threadIdx.x;
    float trow[32];
#pragma unroll
    for (int p = 0; p < 32; p++) trow[p] = trans[n * NTAG + p];
    const float tstop = trans[STOP_TAG * NTAG + n];

    float myfv = (n == START_TAG) ? 0.0f : NEGV;
    float fnext = __ldg(&g_feats[n]);

#pragma unroll 1
    for (int t = 0; t < SEQ; t++) {
        float feat = fnext;
        if (t + 1 < SEQ) fnext = __ldg(&g_feats[(size_t)(t + 1) * NTAG + n]);

        float sc[32];
        int ix[32];
#pragma unroll
        for (int p = 0; p < 32; p++) {
            sc[p] = __shfl_sync(0xffffffffu, myfv, p) + trow[p];
            ix[p] = p;
        }
#pragma unroll
        for (int off = 1; off < 32; off <<= 1) {
#pragma unroll
            for (int i = 0; i < 32; i += 2 * off) {
                if (sc[i + off] > sc[i]) { sc[i] = sc[i + off]; ix[i] = ix[i + off]; }
            }
        }
        myfv = sc[0] + feat;
        bpbuf[t * NTAG + n] = (unsigned char)ix[0];
    }

    float bv = myfv + tstop;
    int bi = n;
#pragma unroll
    for (int off = 16; off; off >>= 1) {
        float ov = __shfl_xor_sync(0xffffffffu, bv, off);
        int   oi = __shfl_xor_sync(0xffffffffu, bi, off);
        if (ov > bv || (ov == bv && oi < bi)) { bv = ov; bi = oi; }
    }

    if (n == 0) {
        const bool has_score = (out_size >= SEQ + 1);
        const int base = has_score ? 1 : 0;
        if (has_score && out_size > 0) out[0] = bv;
        int idx = bi;
        for (int t = SEQ - 1; t >= 0; t--) {
            int o = base + t;
            if (o < out_size) out[o] = (float)idx;
            idx = bpbuf[t * NTAG + idx];
        }
    }
}

// ---------------- launch ----------------
extern "C" void kernel_launch(void* const* d_in, const int* in_sizes, int n_in,
                              void* d_out, int out_size)
{
    const int*   sentence = (const int*)  d_in[0];
    const float* h0       = (const float*)d_in[1];
    const float* c0       = (const float*)d_in[2];
    const float* embedding= (const float*)d_in[3];
    const float* w_ih_f   = (const float*)d_in[4];
    const float* w_hh_f   = (const float*)d_in[5];
    const float* b_f      = (const float*)d_in[6];
    const float* w_ih_b   = (const float*)d_in[7];
    const float* w_hh_b   = (const float*)d_in[8];
    const float* b_b      = (const float*)d_in[9];
    const float* lin_w    = (const float*)d_in[10];
    const float* lin_b    = (const float*)d_in[11];
    const float* trans    = (const float*)d_in[12];
    float* out = (float*)d_out;

    xg_kernel<<<dim3(SEQ / 16, 2), 256>>>(sentence, embedding, w_ih_f, b_f, w_ih_b, b_b);
    lstm_kernel<<<16, 512>>>(w_hh_f, w_hh_b, h0, c0);
    feats_kernel<<<SEQ, 256>>>(lin_w, lin_b);

    const int vit_smem = SEQ * NTAG;   // 128 KB backpointers
    cudaFuncSetAttribute(viterbi_kernel, cudaFuncAttributeMaxDynamicSharedMemorySize, vit_smem);
    viterbi_kernel<<<1, 32, vit_smem>>>(trans, out, out_size);
}